// round 9
// baseline (speedup 1.0000x reference)
#include <cuda_runtime.h>
#include <cstdint>

#define IN_F   2048
#define OUT_F  512
#define NBITS  8
#define BATCH  8
#define NFB    (IN_F / 16)        // 128 f-blocks, 16 f-steps per packed word
#define WCOLS  (OUT_F * 4)        // 2048 words per f-block row (one per (o,sub))

// 1 MB packed bits: g_W2[fb*WCOLS + o*4 + sub]
// bit (2j+i) of word = (weight[16*fb+j, o*8 + 2*sub + i] >= 0.5)
__device__ uint32_t g_W2[NFB * WCOLS];

// ---------------------------------------------------------------------------
// Kernel A: binarize + pack. One thread per output word. Coalesced, DRAM-bound.
// ---------------------------------------------------------------------------
__global__ void pack2_kernel(const float* __restrict__ weight) {
    int tid = blockIdx.x * blockDim.x + threadIdx.x;
    if (tid >= NFB * WCOLS) return;
    int o4 = tid & (WCOLS - 1);
    int fb = tid >> 11;
    const float2* wp = reinterpret_cast<const float2*>(weight);
    uint32_t word = 0;
#pragma unroll
    for (int j = 0; j < 16; ++j) {
        int f = fb * 16 + j;
        float2 v = wp[(size_t)f * (OUT_F * NBITS / 2) + o4];
        word |= (v.x >= 0.5f ? 1u : 0u) << (2 * j);
        word |= (v.y >= 0.5f ? 1u : 0u) << (2 * j + 1);
    }
    g_W2[tid] = word;
}

// ---------------------------------------------------------------------------
// Kernel B: skewed-pipeline CSA scan. 4 threads per (b,o) pair, 2 bit-lanes
// each. Thread `sub` processes f-block i during iteration it = i + sub.
// Cross-thread carries (single bits, since t~ in [0,2) -> h in {0,1}) are
// packed 16-per-uint32 and moved by ONE shfl per block, so the per-step
// recurrence is register-only: t~ = (s~+a~)+c~; p = t~>=1;
// s~' = p ? t~-1 : t~ (Sterbenz-exact); carry-out bit = p.
// Bit-identical algebra to R2 (validated rel_err 0.0).
// ---------------------------------------------------------------------------
__global__ __launch_bounds__(128, 1)
void csa3_kernel(const float* __restrict__ x, float* __restrict__ out) {
    __shared__ float4 xs4[IN_F / 4];

    const int tid = threadIdx.x;
    const int sub = tid & 3;           // lane-pair owner: bit lanes 2sub, 2sub+1
    const int pl  = tid >> 2;          // pair index within block (0..31)
    const int b   = blockIdx.x >> 4;   // 128 blocks = 8 b * 16 o-groups
    const int og  = blockIdx.x & 15;
    const int o   = og * 32 + pl;

    // Stage halved x row into shared (vectorized)
    const float4* xr4 = reinterpret_cast<const float4*>(x + (size_t)b * IN_F);
    for (int i = tid; i < IN_F / 4; i += 128) {
        float4 v = xr4[i];
        v.x *= 0.5f; v.y *= 0.5f; v.z *= 0.5f; v.w *= 0.5f;
        xs4[i] = v;
    }
    __syncthreads();

    const uint32_t* Wp = g_W2 + (o * 4 + sub);

    float    s0 = 0.0f, s1 = 0.0f;     // halved sum state for lanes k0, k1
    float    c01f = 0.0f;              // own k0 -> k1 halved carry (prev step)
    uint32_t cpack_out = 0;            // packet sent to thread sub+1
    uint32_t prevtop   = 0;            // h_k1 of last step of previous block

    // depth-2 prefetch of this thread's own weight words (blocks 0,1)
    uint32_t wbuf0 = Wp[0];
    uint32_t wbuf1 = Wp[WCOLS];
    int      nload = 2;                // next block index to load

    for (int it = 0; it < NFB + 3; ++it) {
        // all threads, converged: receive neighbor's packed carries
        uint32_t cin_pk = __shfl_up_sync(0xffffffffu, cpack_out, 1);
        if (sub == 0) cin_pk = 0;      // overall lane0 has carry-in 0

        const int i = it - sub;        // this thread's f-block this iteration
        if (0 <= i && i < NFB) {
            const uint32_t wcur = wbuf0;
            wbuf0 = wbuf1;
            int nid = (nload < NFB) ? nload : (NFB - 1);
            wbuf1 = Wp[(size_t)nid * WCOLS];
            ++nload;

            uint32_t hb = 0;           // outgoing carry bits (h of lane k1)
#pragma unroll
            for (int q = 0; q < 4; ++q) {
                const float4 xv = xs4[i * 4 + q];
                const float xq[4] = {xv.x, xv.y, xv.z, xv.w};
#pragma unroll
                for (int r = 0; r < 4; ++r) {
                    const int   j  = q * 4 + r;
                    const float xh = xq[r];
                    const float a0  = (wcur  & (1u << (2 * j)))     ? xh   : 0.0f;
                    const float a1  = (wcur  & (1u << (2 * j + 1))) ? xh   : 0.0f;
                    const float ci0 = (cin_pk & (1u << j))          ? 0.5f : 0.0f;
                    const float t0 = (s0 + a0) + ci0;
                    const float t1 = (s1 + a1) + c01f;
                    const bool  p0 = (t0 >= 1.0f);
                    const bool  p1 = (t1 >= 1.0f);
                    s0   = p0 ? (t0 - 1.0f) : t0;   // exact frac on [0,2)
                    s1   = p1 ? (t1 - 1.0f) : t1;
                    c01f = p0 ? 0.5f : 0.0f;
                    hb  |= p1 ? (1u << j) : 0u;
                }
            }
            // consumer's step 16i+j needs producer h at step 16i+j-1:
            // shift left by one, splice in last bit of previous block
            cpack_out = (hb << 1) | prevtop;
            prevtop   = hb >> 15;
        }
    }

    // final carry for lane k0 = neighbor's h_k1 at step 2047 = neighbor prevtop
    uint32_t nb = __shfl_up_sync(0xffffffffu, prevtop, 1);
    if (sub == 0) nb = 0;

    const int pair = b * OUT_F + o;
    float2* so = reinterpret_cast<float2*>(out + (size_t)pair * 8 + 2 * sub);
    *so = make_float2(2.0f * s0, 2.0f * s1);
    float2* co = reinterpret_cast<float2*>(
        out + (size_t)(BATCH * OUT_F * NBITS) + (size_t)pair * 8 + 2 * sub);
    *co = make_float2((float)nb, 2.0f * c01f);   // h values are exactly 0/1
}

// ---------------------------------------------------------------------------
extern "C" void kernel_launch(void* const* d_in, const int* in_sizes, int n_in,
                              void* d_out, int out_size) {
    const float* x = (const float*)d_in[0];
    const float* w = (const float*)d_in[1];
    if (n_in >= 2 && in_sizes[0] > in_sizes[1]) {  // defensive: x=16K, weight=8.4M
        const float* t = x; x = w; w = t;
    }
    float* out = (float*)d_out;

    pack2_kernel<<<(NFB * WCOLS + 255) / 256, 256>>>(w);
    csa3_kernel<<<BATCH * 16, 128>>>(x, out);
}